// round 17
// baseline (speedup 1.0000x reference)
#include <cuda_runtime.h>
#include <cuda_bf16.h>
#include <cstdint>
#include <cstddef>

#define NNODES 20000
#define NEDGES 200000
#define DIMC   256
#define INNERC 256
#define EDIMC  512
#define FFC    1024
#define OUTC   128

// ---------------------------------------------------------------------------
// Scratch (static device allocations — allowed)
// ---------------------------------------------------------------------------
__device__ float g_xn  [NNODES * DIMC];
__device__ float g_q   [NNODES * INNERC];
__device__ float g_kv  [NNODES * 2 * INNERC];
__device__ float g_e   [(size_t)NEDGES * INNERC];
__device__ float g_sim [NEDGES * 4];
__device__ float g_agg [NNODES * INNERC];
__device__ float g_y   [NNODES * DIMC];
__device__ float g_x   [NNODES * DIMC];
__device__ float g_ff  [NNODES * FFC];
__device__ int   g_deg   [NNODES];
__device__ int   g_rowptr[NNODES + 1];
__device__ int   g_cursor[NNODES];
__device__ int   g_col   [NEDGES];

// ---------------------------------------------------------------------------
// Helpers
// ---------------------------------------------------------------------------
__device__ __forceinline__ float gelu_f(float t) {
    float t3 = t * t * t;
    return 0.5f * t * (1.0f + tanhf(0.7978845608028654f * (t + 0.044715f * t3)));
}

__device__ __forceinline__ void mma16816(float* c, const uint32_t* a,
                                         uint32_t b0, uint32_t b1) {
    asm volatile("mma.sync.aligned.m16n8k16.row.col.f32.bf16.bf16.f32 "
                 "{%0,%1,%2,%3}, {%4,%5,%6,%7}, {%8,%9}, {%0,%1,%2,%3};"
                 : "+f"(c[0]), "+f"(c[1]), "+f"(c[2]), "+f"(c[3])
                 : "r"(a[0]), "r"(a[1]), "r"(a[2]), "r"(a[3]), "r"(b0), "r"(b1));
}

// split a,b into packed bf16 hi pair and lo pair
__device__ __forceinline__ void split2(float a, float b, uint32_t& hi, uint32_t& lo) {
    __nv_bfloat16 ha = __float2bfloat16(a);
    __nv_bfloat16 hb = __float2bfloat16(b);
    __nv_bfloat16 la = __float2bfloat16(a - __bfloat162float(ha));
    __nv_bfloat16 lb = __float2bfloat16(b - __bfloat162float(hb));
    hi = (uint32_t)__bfloat16_as_ushort(ha) | ((uint32_t)__bfloat16_as_ushort(hb) << 16);
    lo = (uint32_t)__bfloat16_as_ushort(la) | ((uint32_t)__bfloat16_as_ushort(lb) << 16);
}

// ---------------------------------------------------------------------------
// Tensor-core GEMM (bf16 split hi/lo, fp32 accumulate):
// C[M,N] = A[M,K] @ W[K,N] + bias ; optional GELU epilogue.
// Requires N % 128 == 0, K % 32 == 0 (true at all call sites). M guarded.
// Block: 128x128 tile, BK=32, 512 threads = 16 warps in 4x4 grid,
// warp tile 32x32 via 2x4 m16n8k16 mma per k16 chunk, 3 passes (hh, hl, lh).
// ---------------------------------------------------------------------------
#define GPAD 40   // halves per smem row (conflict-free for frag LDS pattern)

template<int GELU>
__global__ __launch_bounds__(512)
void gemm_bf16_kernel(const float* __restrict__ A, const float* __restrict__ W,
                      const float* __restrict__ bias, float* __restrict__ C,
                      int M, int K, int N)
{
    __shared__ __nv_bfloat16 As_hi[128 * GPAD];
    __shared__ __nv_bfloat16 As_lo[128 * GPAD];
    __shared__ __nv_bfloat16 Bs_hi[128 * GPAD];
    __shared__ __nv_bfloat16 Bs_lo[128 * GPAD];

    const int tid   = threadIdx.x;
    const int wid   = tid >> 5;
    const int lane  = tid & 31;
    const int warp_m = wid >> 2;     // 0..3
    const int warp_n = wid & 3;      // 0..3
    const int g = lane >> 2;         // 0..7
    const int t = lane & 3;          // 0..3

    const int row0 = blockIdx.y * 128;
    const int col0 = blockIdx.x * 128;

    float acc[2][4][4];
#pragma unroll
    for (int mi = 0; mi < 2; mi++)
#pragma unroll
        for (int ni = 0; ni < 4; ni++)
#pragma unroll
            for (int j = 0; j < 4; j++) acc[mi][ni][j] = 0.0f;

    for (int k0 = 0; k0 < K; k0 += 32) {
        // ---- load + split A tile: 128 rows x 32 fp32 ----
#pragma unroll
        for (int s = 0; s < 2; s++) {
            int f4 = tid + s * 512;          // 0..1023 over 128x8 float4
            int r  = f4 >> 3;
            int kk = (f4 & 7) << 2;
            float4 v = make_float4(0.f, 0.f, 0.f, 0.f);
            if (row0 + r < M)
                v = *reinterpret_cast<const float4*>(A + (size_t)(row0 + r) * K + k0 + kk);
            uint32_t h0, h1, l0, l1;
            split2(v.x, v.y, h0, l0);
            split2(v.z, v.w, h1, l1);
            *reinterpret_cast<uint2*>(&As_hi[r * GPAD + kk]) = make_uint2(h0, h1);
            *reinterpret_cast<uint2*>(&As_lo[r * GPAD + kk]) = make_uint2(l0, l1);
        }
        // ---- load + split + transpose W tile: 32 k-rows x 128 cols ----
#pragma unroll
        for (int s = 0; s < 2; s++) {
            int f4 = tid + s * 512;          // over 32x32 float4
            int kr = f4 >> 5;
            int nn = (f4 & 31) << 2;
            float4 v = *reinterpret_cast<const float4*>(W + (size_t)(k0 + kr) * N + col0 + nn);
            float vv[4] = {v.x, v.y, v.z, v.w};
#pragma unroll
            for (int j = 0; j < 4; j++) {
                __nv_bfloat16 h = __float2bfloat16(vv[j]);
                __nv_bfloat16 l = __float2bfloat16(vv[j] - __bfloat162float(h));
                Bs_hi[(nn + j) * GPAD + kr] = h;
                Bs_lo[(nn + j) * GPAD + kr] = l;
            }
        }
        __syncthreads();

#pragma unroll
        for (int ks = 0; ks < 2; ks++) {
            const int kb = ks * 16 + 2 * t;
            uint32_t ahi[2][4], alo[2][4];
#pragma unroll
            for (int mi = 0; mi < 2; mi++) {
                int rb = (warp_m * 32 + mi * 16 + g) * GPAD + kb;
                ahi[mi][0] = *reinterpret_cast<const uint32_t*>(&As_hi[rb]);
                ahi[mi][1] = *reinterpret_cast<const uint32_t*>(&As_hi[rb + 8 * GPAD]);
                ahi[mi][2] = *reinterpret_cast<const uint32_t*>(&As_hi[rb + 8]);
                ahi[mi][3] = *reinterpret_cast<const uint32_t*>(&As_hi[rb + 8 * GPAD + 8]);
                alo[mi][0] = *reinterpret_cast<const uint32_t*>(&As_lo[rb]);
                alo[mi][1] = *reinterpret_cast<const uint32_t*>(&As_lo[rb + 8 * GPAD]);
                alo[mi][2] = *reinterpret_cast<const uint32_t*>(&As_lo[rb + 8]);
                alo[mi][3] = *reinterpret_cast<const uint32_t*>(&As_lo[rb + 8 * GPAD + 8]);
            }
#pragma unroll
            for (int ni = 0; ni < 4; ni++) {
                int nb = (warp_n * 32 + ni * 8 + g) * GPAD + kb;
                uint32_t bh0 = *reinterpret_cast<const uint32_t*>(&Bs_hi[nb]);
                uint32_t bh1 = *reinterpret_cast<const uint32_t*>(&Bs_hi[nb + 8]);
                uint32_t bl0 = *reinterpret_cast<const uint32_t*>(&Bs_lo[nb]);
                uint32_t bl1 = *reinterpret_cast<const uint32_t*>(&Bs_lo[nb + 8]);
#pragma unroll
                for (int mi = 0; mi < 2; mi++) {
                    mma16816(acc[mi][ni], ahi[mi], bh0, bh1);
                    mma16816(acc[mi][ni], ahi[mi], bl0, bl1);
                    mma16816(acc[mi][ni], alo[mi], bh0, bh1);
                }
            }
        }
        __syncthreads();
    }

    // ---- epilogue ----
#pragma unroll
    for (int mi = 0; mi < 2; mi++) {
        int r1 = row0 + warp_m * 32 + mi * 16 + g;
        int r2 = r1 + 8;
#pragma unroll
        for (int ni = 0; ni < 4; ni++) {
            int gc = col0 + warp_n * 32 + ni * 8 + 2 * t;
            float b0 = bias[gc], b1 = bias[gc + 1];
            float o0 = acc[mi][ni][0] + b0;
            float o1 = acc[mi][ni][1] + b1;
            float o2 = acc[mi][ni][2] + b0;
            float o3 = acc[mi][ni][3] + b1;
            if (GELU) {
                o0 = gelu_f(o0); o1 = gelu_f(o1);
                o2 = gelu_f(o2); o3 = gelu_f(o3);
            }
            if (r1 < M) *reinterpret_cast<float2*>(C + (size_t)r1 * N + gc) = make_float2(o0, o1);
            if (r2 < M) *reinterpret_cast<float2*>(C + (size_t)r2 * N + gc) = make_float2(o2, o3);
        }
    }
}

// ---------------------------------------------------------------------------
// LayerNorm: one warp per row (256 cols).
// ---------------------------------------------------------------------------
__global__ void ln_kernel(const float* __restrict__ x, const float* __restrict__ g,
                          const float* __restrict__ b, float* __restrict__ out, int rows)
{
    int r    = (blockIdx.x * blockDim.x + threadIdx.x) >> 5;
    int lane = threadIdx.x & 31;
    if (r >= rows) return;
    const float* xr = x + (size_t)r * DIMC;
    float v[8];
    float s = 0.f, s2 = 0.f;
#pragma unroll
    for (int i = 0; i < 8; i++) {
        v[i] = xr[lane + 32 * i];
        s  += v[i];
        s2 += v[i] * v[i];
    }
#pragma unroll
    for (int o = 16; o > 0; o >>= 1) {
        s  += __shfl_xor_sync(0xffffffffu, s,  o);
        s2 += __shfl_xor_sync(0xffffffffu, s2, o);
    }
    float mean = s * (1.f / 256.f);
    float var  = s2 * (1.f / 256.f) - mean * mean;
    float rs   = rsqrtf(var + 1e-5f);
    float* orow = out + (size_t)r * DIMC;
#pragma unroll
    for (int i = 0; i < 8; i++) {
        int c = lane + 32 * i;
        orow[c] = (v[i] - mean) * rs * g[c] + b[c];
    }
}

// ---------------------------------------------------------------------------
// Edge similarity: one warp per edge. sim[e][h] = scale * <q[dst], k[src]+e>
// ---------------------------------------------------------------------------
__global__ void sim_kernel(const float* __restrict__ q, const float* __restrict__ kv,
                           const float* __restrict__ ebuf, const int* __restrict__ src,
                           const int* __restrict__ dst, float* __restrict__ sim)
{
    int eid  = (blockIdx.x * blockDim.x + threadIdx.x) >> 5;
    int lane = threadIdx.x & 31;
    if (eid >= NEDGES) return;
    int s = src[eid], t = dst[eid];
    const float* qr = q    + (size_t)t   * INNERC;
    const float* kr = kv   + (size_t)s   * (2 * INNERC);
    const float* er = ebuf + (size_t)eid * INNERC;
    const float scale = 0.125f;  // 64^-0.5
#pragma unroll
    for (int h = 0; h < 4; h++) {
        int j = h * 64 + lane;
        float p = qr[j]      * (kr[j]      + er[j])
                + qr[j + 32] * (kr[j + 32] + er[j + 32]);
#pragma unroll
        for (int o = 16; o > 0; o >>= 1) p += __shfl_xor_sync(0xffffffffu, p, o);
        if (lane == 0) sim[eid * 4 + h] = p * scale;
    }
}

// ---------------------------------------------------------------------------
// Per-node segment softmax + weighted aggregation over incoming edges (CSR).
// ---------------------------------------------------------------------------
__global__ __launch_bounds__(256)
void node_attn_kernel(const float* __restrict__ kv, const float* __restrict__ ebuf,
                      const float* __restrict__ sim, const int* __restrict__ rowptr,
                      const int* __restrict__ col, const int* __restrict__ src,
                      float* __restrict__ agg)
{
    int n = blockIdx.x;
    int start = rowptr[n], end = rowptr[n + 1];
    int tid = threadIdx.x;

    __shared__ float sm[4], sinv[4];
    __shared__ float w[64 * 4];
    __shared__ int esh[64], ssh[64];

    int wid = tid >> 5, lane = tid & 31;
    if (wid < 4) {
        float mx = -1e30f;
        for (int p = start + lane; p < end; p += 32)
            mx = fmaxf(mx, sim[col[p] * 4 + wid]);
#pragma unroll
        for (int o = 16; o > 0; o >>= 1) mx = fmaxf(mx, __shfl_xor_sync(0xffffffffu, mx, o));
        float dn = 0.f;
        for (int p = start + lane; p < end; p += 32)
            dn += __expf(sim[col[p] * 4 + wid] - mx);
#pragma unroll
        for (int o = 16; o > 0; o >>= 1) dn += __shfl_xor_sync(0xffffffffu, dn, o);
        if (lane == 0) {
            sm[wid]   = mx;
            sinv[wid] = (dn > 0.f) ? 1.f / dn : 0.f;
        }
    }
    __syncthreads();

    int c = tid, h = tid >> 6;
    float acc = 0.f;
    for (int base = start; base < end; base += 64) {
        int cnt = min(64, end - base);
        if (tid < cnt * 4) {
            int i = tid >> 2, hh = tid & 3;
            int eid = col[base + i];
            w[tid] = __expf(sim[eid * 4 + hh] - sm[hh]) * sinv[hh];
            if (hh == 0) { esh[i] = eid; ssh[i] = src[eid]; }
        }
        __syncthreads();
        for (int i = 0; i < cnt; i++) {
            int eid = esh[i], s = ssh[i];
            acc = fmaf(w[i * 4 + h],
                       kv[(size_t)s * (2 * INNERC) + INNERC + c] + ebuf[(size_t)eid * INNERC + c],
                       acc);
        }
        __syncthreads();
    }
    agg[(size_t)n * INNERC + c] = acc;
}

// ---------------------------------------------------------------------------
// Gated residual: x = y*g + x*(1-g), g = sigmoid(<[y,x,y-x], gw>). Warp per row.
// ---------------------------------------------------------------------------
__global__ void gated_residual_kernel(const float* __restrict__ y, float* __restrict__ x,
                                      const float* __restrict__ gw, int rows)
{
    int r    = (blockIdx.x * blockDim.x + threadIdx.x) >> 5;
    int lane = threadIdx.x & 31;
    if (r >= rows) return;
    const float* yr = y + (size_t)r * DIMC;
    float* xr = x + (size_t)r * DIMC;
    float yv[8], rv[8];
    float s = 0.f;
#pragma unroll
    for (int i = 0; i < 8; i++) {
        int c = lane + 32 * i;
        yv[i] = yr[c];
        rv[i] = xr[c];
        s += yv[i] * (gw[c] + gw[512 + c]) + rv[i] * (gw[256 + c] - gw[512 + c]);
    }
#pragma unroll
    for (int o = 16; o > 0; o >>= 1) s += __shfl_xor_sync(0xffffffffu, s, o);
    float gate = 1.f / (1.f + __expf(-s));
#pragma unroll
    for (int i = 0; i < 8; i++) {
        int c = lane + 32 * i;
        xr[c] = yv[i] * gate + rv[i] * (1.f - gate);
    }
}

// ---------------------------------------------------------------------------
// CSR build
// ---------------------------------------------------------------------------
__global__ void zero_int_kernel(int* p, int n) {
    int i = blockIdx.x * blockDim.x + threadIdx.x;
    if (i < n) p[i] = 0;
}

__global__ void count_deg_kernel(const int* __restrict__ dst, int* __restrict__ deg) {
    int e = blockIdx.x * blockDim.x + threadIdx.x;
    if (e < NEDGES) atomicAdd(&deg[dst[e]], 1);
}

__global__ void scan_deg_kernel(const int* __restrict__ deg, int* __restrict__ rowptr,
                                int* __restrict__ cursor)
{
    __shared__ int temp[1024];
    __shared__ int carry;
    int tid = threadIdx.x;
    if (tid == 0) carry = 0;
    __syncthreads();
    for (int base = 0; base < NNODES; base += 1024) {
        int i = base + tid;
        int v = (i < NNODES) ? deg[i] : 0;
        temp[tid] = v;
        __syncthreads();
        for (int off = 1; off < 1024; off <<= 1) {
            int t = (tid >= off) ? temp[tid - off] : 0;
            __syncthreads();
            temp[tid] += t;
            __syncthreads();
        }
        int excl = temp[tid] - v;
        if (i < NNODES) {
            int r = carry + excl;
            rowptr[i] = r;
            cursor[i] = r;
        }
        __syncthreads();
        if (tid == 1023) carry += temp[1023];
        __syncthreads();
    }
    if (tid == 0) rowptr[NNODES] = carry;
}

__global__ void fill_col_kernel(const int* __restrict__ dst, int* __restrict__ cursor,
                                int* __restrict__ col)
{
    int e = blockIdx.x * blockDim.x + threadIdx.x;
    if (e < NEDGES) {
        int pos = atomicAdd(&cursor[dst[e]], 1);
        col[pos] = e;
    }
}

__global__ void copy_kernel(const float* __restrict__ in, float* __restrict__ out, int n) {
    for (int i = blockIdx.x * blockDim.x + threadIdx.x; i < n; i += gridDim.x * blockDim.x)
        out[i] = in[i];
}

// ---------------------------------------------------------------------------
// Host launch
// ---------------------------------------------------------------------------
extern "C" void kernel_launch(void* const* d_in, const int* in_sizes, int n_in,
                              void* d_out, int out_size)
{
    const float* x         = (const float*)d_in[0];
    const float* edge_attr = (const float*)d_in[1];
    const int*   edge_idx  = (const int*)  d_in[2];
    const float* ln1_g = (const float*)d_in[3];
    const float* ln1_b = (const float*)d_in[4];
    const float* Wq  = (const float*)d_in[5];
    const float* bq  = (const float*)d_in[6];
    const float* Wkv = (const float*)d_in[7];
    const float* bkv = (const float*)d_in[8];
    const float* We  = (const float*)d_in[9];
    const float* be  = (const float*)d_in[10];
    const float* Wo  = (const float*)d_in[11];
    const float* bo  = (const float*)d_in[12];
    const float* gaw = (const float*)d_in[13];
    const float* ln2_g = (const float*)d_in[14];
    const float* ln2_b = (const float*)d_in[15];
    const float* Wff1 = (const float*)d_in[16];
    const float* bff1 = (const float*)d_in[17];
    const float* Wff2 = (const float*)d_in[18];
    const float* bff2 = (const float*)d_in[19];
    const float* gfw  = (const float*)d_in[20];
    const float* Wproj = (const float*)d_in[21];
    const float* bproj = (const float*)d_in[22];
    float* out = (float*)d_out;

    const int* src = edge_idx;
    const int* dst = edge_idx + NEDGES;

    float *xn, *qb, *kvb, *eb, *simb, *aggb, *yb, *xb, *ffb;
    int *deg, *rowptr, *cursor, *colb;
    cudaGetSymbolAddress((void**)&xn,     g_xn);
    cudaGetSymbolAddress((void**)&qb,     g_q);
    cudaGetSymbolAddress((void**)&kvb,    g_kv);
    cudaGetSymbolAddress((void**)&eb,     g_e);
    cudaGetSymbolAddress((void**)&simb,   g_sim);
    cudaGetSymbolAddress((void**)&aggb,   g_agg);
    cudaGetSymbolAddress((void**)&yb,     g_y);
    cudaGetSymbolAddress((void**)&xb,     g_x);
    cudaGetSymbolAddress((void**)&ffb,    g_ff);
    cudaGetSymbolAddress((void**)&deg,    g_deg);
    cudaGetSymbolAddress((void**)&rowptr, g_rowptr);
    cudaGetSymbolAddress((void**)&cursor, g_cursor);
    cudaGetSymbolAddress((void**)&colb,   g_col);

    const int TB = 256;
    const int edgeBlocks = (NEDGES + TB - 1) / TB;
    const int nodeBlocks = (NNODES + TB - 1) / TB;
    const int warpRowBlocks = (NNODES * 32 + TB - 1) / TB;
    const int warpEdgeBlocks = ((size_t)NEDGES * 32 + TB - 1) / TB;

    // --- CSR build ---
    zero_int_kernel<<<nodeBlocks, TB>>>(deg, NNODES);
    count_deg_kernel<<<edgeBlocks, TB>>>(dst, deg);
    scan_deg_kernel<<<1, 1024>>>(deg, rowptr, cursor);
    fill_col_kernel<<<edgeBlocks, TB>>>(dst, cursor, colb);

    // x working copy
    copy_kernel<<<512, TB>>>(x, xb, NNODES * DIMC);

    auto gemm_grid = [](int M, int N) { return dim3((unsigned)(N / 128), (unsigned)((M + 127) / 128)); };

    for (int d = 0; d < 2; d++) {
        // --- attention block ---
        ln_kernel<<<warpRowBlocks, TB>>>(xb, ln1_g + d * DIMC, ln1_b + d * DIMC, xn, NNODES);

        gemm_bf16_kernel<0><<<gemm_grid(NNODES, INNERC), 512>>>(
            xn, Wq + (size_t)d * DIMC * INNERC, bq + d * INNERC, qb, NNODES, DIMC, INNERC);
        gemm_bf16_kernel<0><<<gemm_grid(NNODES, 2 * INNERC), 512>>>(
            xn, Wkv + (size_t)d * DIMC * 2 * INNERC, bkv + d * 2 * INNERC, kvb, NNODES, DIMC, 2 * INNERC);
        gemm_bf16_kernel<0><<<gemm_grid(NEDGES, INNERC), 512>>>(
            edge_attr, We + (size_t)d * EDIMC * INNERC, be + d * INNERC, eb, NEDGES, EDIMC, INNERC);

        sim_kernel<<<warpEdgeBlocks, TB>>>(qb, kvb, eb, src, dst, simb);
        node_attn_kernel<<<NNODES, TB>>>(kvb, eb, simb, rowptr, colb, src, aggb);

        gemm_bf16_kernel<0><<<gemm_grid(NNODES, DIMC), 512>>>(
            aggb, Wo + (size_t)d * INNERC * DIMC, bo + d * DIMC, yb, NNODES, INNERC, DIMC);
        gated_residual_kernel<<<warpRowBlocks, TB>>>(yb, xb, gaw + d * 3 * DIMC, NNODES);

        // --- feedforward block ---
        ln_kernel<<<warpRowBlocks, TB>>>(xb, ln2_g + d * DIMC, ln2_b + d * DIMC, xn, NNODES);
        gemm_bf16_kernel<1><<<gemm_grid(NNODES, FFC), 512>>>(
            xn, Wff1 + (size_t)d * DIMC * FFC, bff1 + d * FFC, ffb, NNODES, DIMC, FFC);
        gemm_bf16_kernel<0><<<gemm_grid(NNODES, DIMC), 512>>>(
            ffb, Wff2 + (size_t)d * FFC * DIMC, bff2 + d * DIMC, yb, NNODES, FFC, DIMC);
        gated_residual_kernel<<<warpRowBlocks, TB>>>(yb, xb, gfw + d * 3 * DIMC, NNODES);
    }

    // --- output projection ---
    gemm_bf16_kernel<0><<<gemm_grid(NNODES, OUTC), 512>>>(
        xb, Wproj, bproj, out, NNODES, DIMC, OUTC);
}